// round 6
// baseline (speedup 1.0000x reference)
#include <cuda_runtime.h>
#include <math.h>

#define T_DIM 1024
#define S_DIM 128
#define H_DIM 512
#define LN_EPS 1e-5f

// Scratch (allocation-free rule: __device__ global)
__device__ float d_gs[S_DIM * H_DIM];   // struct @ ws^T  (128 x 512)

// ---------------------------------------------------------------------------
// gs = struct @ ws^T  (small: 33M MAC). Tile 32(M=s) x 32(N=h), K=512.
// 256 threads, 4 outputs each (1 row x float4). grid (16, 4) = 64 blocks.
// ---------------------------------------------------------------------------
#define SBK 32

__global__ __launch_bounds__(256) void gs_kernel(
    const float* __restrict__ sstruct, const float* __restrict__ W)
{
    __shared__ float As[32][36];
    __shared__ float Ws[SBK][36];

    const int tid = threadIdx.x;
    const int r   = tid >> 3;          // 0..31
    const int c4  = (tid & 7) * 4;     // 0,4,...,28
    const int h0  = blockIdx.x * 32;
    const int s0  = blockIdx.y * 32;

    const float* Aptr = sstruct + (size_t)(s0 + r) * H_DIM;
    const float* Wptr = W + (size_t)(h0 + r) * 1024 + H_DIM;   // ws half

    float acc[4] = {0.f, 0.f, 0.f, 0.f};

    float4 na = *(const float4*)(Aptr + c4);
    float4 nw = *(const float4*)(Wptr + c4);
    for (int k0 = 0; k0 < H_DIM; k0 += SBK) {
        *(float4*)&As[r][c4] = na;
        Ws[c4 + 0][r] = nw.x; Ws[c4 + 1][r] = nw.y;
        Ws[c4 + 2][r] = nw.z; Ws[c4 + 3][r] = nw.w;
        __syncthreads();
        if (k0 + SBK < H_DIM) {
            na = *(const float4*)(Aptr + k0 + SBK + c4);
            nw = *(const float4*)(Wptr + k0 + SBK + c4);
        }
        #pragma unroll
        for (int k = 0; k < SBK; k++) {
            float  a = As[r][k];
            float4 b = *(const float4*)&Ws[k][c4];
            acc[0] = fmaf(a, b.x, acc[0]);
            acc[1] = fmaf(a, b.y, acc[1]);
            acc[2] = fmaf(a, b.z, acc[2]);
            acc[3] = fmaf(a, b.w, acc[3]);
        }
        __syncthreads();
    }
    *(float4*)(d_gs + (size_t)(s0 + r) * H_DIM + h0 + c4) =
        make_float4(acc[0], acc[1], acc[2], acc[3]);
}

// ---------------------------------------------------------------------------
// fuse3: per block (h0, t0):
//   Phase A: compute gt tile (TT x HC) = text[t0:,:] @ gate_w[h0:,:512]^T
//            in-block (zero redundancy), + bias, into smem.
//   Phase B: store-only hot loop: gates STG.128 streaming + enrichment accum
//            from smem-resident gs/struct chunks; x = text + enrichment.
// TT=32, HC=32, 256 threads, grid (16, 32) = 512 blocks.
// ---------------------------------------------------------------------------
#define HC 32
#define TT 32
#define BK 32

__global__ __launch_bounds__(256) void fuse3_kernel(
    const float* __restrict__ text,
    const float* __restrict__ sstruct,
    const int*   __restrict__ mask,
    const float* __restrict__ gate_w,
    const float* __restrict__ gate_b,
    float* __restrict__ xout,       // (T, H) = text + enrichment (pre-LN)
    float* __restrict__ gates)      // (T, S, H)
{
    __shared__ float gt_s[TT][36];                    // 4.6 KB
    __shared__ unsigned char msk_b[TT][S_DIM];        // 4 KB
    __shared__ __align__(16) float buf[2 * S_DIM * HC];  // 32 KB (aliased)

    float (*As)[36] = (float (*)[36])buf;             // phase A staging
    float (*Ws)[36] = (float (*)[36])(buf + TT * 36);

    const int tid = threadIdx.x;
    const int h0  = blockIdx.x * HC;
    const int t0  = blockIdx.y * TT;

    // ---- mask pack: TT*S bytes = 1024 words, 4 per thread (msk_b only) ----
    #pragma unroll
    for (int i = 0; i < 4; i++) {
        int widx = tid + i * 256;
        int row  = widx >> 5;            // 32 words per row
        int s4   = (widx & 31) * 4;
        int4 mv = *(const int4*)(mask + (size_t)(t0 + row) * S_DIM + s4);
        unsigned p = (mv.x != 0 ? 1u : 0u)
                   | (mv.y != 0 ? 0x100u : 0u)
                   | (mv.z != 0 ? 0x10000u : 0u)
                   | (mv.w != 0 ? 0x1000000u : 0u);
        ((unsigned*)msk_b)[widx] = p;
    }

    // ---- Phase A: gt tile GEMM (TT x HC, K=512) ----
    const int r  = tid >> 3;             // 0..31 (t-row)
    const int c4 = (tid & 7) * 4;        // 0..28 (h-col group)

    const float* Aptr = text   + (size_t)(t0 + r) * H_DIM;
    const float* Wptr = gate_w + (size_t)(h0 + r) * 1024;   // wt half

    float acc[4] = {0.f, 0.f, 0.f, 0.f};

    float4 na = *(const float4*)(Aptr + c4);
    float4 nw = *(const float4*)(Wptr + c4);
    for (int k0 = 0; k0 < H_DIM; k0 += BK) {
        *(float4*)&As[r][c4] = na;
        Ws[c4 + 0][r] = nw.x; Ws[c4 + 1][r] = nw.y;
        Ws[c4 + 2][r] = nw.z; Ws[c4 + 3][r] = nw.w;
        __syncthreads();
        if (k0 + BK < H_DIM) {
            na = *(const float4*)(Aptr + k0 + BK + c4);
            nw = *(const float4*)(Wptr + k0 + BK + c4);
        }
        #pragma unroll
        for (int k = 0; k < BK; k++) {
            float  a = As[r][k];
            float4 b = *(const float4*)&Ws[k][c4];
            acc[0] = fmaf(a, b.x, acc[0]);
            acc[1] = fmaf(a, b.y, acc[1]);
            acc[2] = fmaf(a, b.z, acc[2]);
            acc[3] = fmaf(a, b.w, acc[3]);
        }
        __syncthreads();
    }
    {
        float4 bias = *(const float4*)(gate_b + h0 + c4);
        float4 g = make_float4(acc[0] + bias.x, acc[1] + bias.y,
                               acc[2] + bias.z, acc[3] + bias.w);
        *(float4*)&gt_s[r][c4] = g;
    }
    __syncthreads();   // As/Ws dead; gt_s complete

    // ---- restage buf as gs/struct chunks (S x HC each) ----
    float (*gs_s)[HC] = (float (*)[HC])buf;
    float (*st_s)[HC] = (float (*)[HC])(buf + S_DIM * HC);
    #pragma unroll
    for (int i = 0; i < 4; i++) {
        int idx = tid + i * 256;         // 0..1023 float4 slots
        int s   = idx >> 3;
        int cc  = (idx & 7) * 4;
        *(float4*)&gs_s[s][cc] = *(const float4*)(d_gs    + (size_t)s * H_DIM + h0 + cc);
        *(float4*)&st_s[s][cc] = *(const float4*)(sstruct + (size_t)s * H_DIM + h0 + cc);
    }
    __syncthreads();

    // ---- Phase B: store-only hot loop ----
    const int hx = tid & 7;              // float4 within chunk
    const int ts = tid >> 3;             // 0..31 t-row
    const int h  = h0 + hx * 4;
    const int rt = t0 + ts;

    const float4 gtb = *(const float4*)&gt_s[ts][hx * 4];
    float4 acc2 = make_float4(0.f, 0.f, 0.f, 0.f);
    float* __restrict__ gp = gates + (size_t)rt * S_DIM * H_DIM + h;

    #pragma unroll 4
    for (int s = 0; s < S_DIM; s++) {
        const float4 gs4 = *(const float4*)&gs_s[s][hx * 4];
        const float4 st4 = *(const float4*)&st_s[s][hx * 4];
        const bool m = msk_b[ts][s] != 0;
        float4 g;
        g.x = m ? fmaxf(gtb.x + gs4.x, 0.f) : 0.f;
        g.y = m ? fmaxf(gtb.y + gs4.y, 0.f) : 0.f;
        g.z = m ? fmaxf(gtb.z + gs4.z, 0.f) : 0.f;
        g.w = m ? fmaxf(gtb.w + gs4.w, 0.f) : 0.f;
        __stcs((float4*)(gp + (size_t)s * H_DIM), g);
        acc2.x = fmaf(g.x, st4.x, acc2.x);
        acc2.y = fmaf(g.y, st4.y, acc2.y);
        acc2.z = fmaf(g.z, st4.z, acc2.z);
        acc2.w = fmaf(g.w, st4.w, acc2.w);
    }

    {
        float4 t4 = *(const float4*)(text + (size_t)rt * H_DIM + h);
        float4 x = make_float4(t4.x + acc2.x, t4.y + acc2.y,
                               t4.z + acc2.z, t4.w + acc2.w);
        *(float4*)(xout + (size_t)rt * H_DIM + h) = x;
    }
}

// ---------------------------------------------------------------------------
// In-place LayerNorm over rows of x. 256 threads, 2 rows per block.
// ---------------------------------------------------------------------------
__global__ __launch_bounds__(256) void ln_kernel(
    float* __restrict__ x,
    const float* __restrict__ gamma,
    const float* __restrict__ beta)
{
    const int tid = threadIdx.x;
    const int h4  = tid & 127;
    const int tg  = tid >> 7;
    const int h   = h4 * 4;
    const int r   = blockIdx.x * 2 + tg;

    __shared__ float red[2][2][4];

    float4 v = *(const float4*)(x + (size_t)r * H_DIM + h);
    float s1 = v.x + v.y + v.z + v.w;
    float s2 = v.x * v.x + v.y * v.y + v.z * v.z + v.w * v.w;

    const int lane = tid & 31;
    const int wg   = (tid >> 5) & 3;
    #pragma unroll
    for (int o = 16; o > 0; o >>= 1) {
        s1 += __shfl_xor_sync(0xFFFFFFFFu, s1, o);
        s2 += __shfl_xor_sync(0xFFFFFFFFu, s2, o);
    }
    if (lane == 0) { red[0][tg][wg] = s1; red[1][tg][wg] = s2; }
    __syncthreads();

    s1 = red[0][tg][0] + red[0][tg][1] + red[0][tg][2] + red[0][tg][3];
    s2 = red[1][tg][0] + red[1][tg][1] + red[1][tg][2] + red[1][tg][3];
    float mu  = s1 * (1.f / H_DIM);
    float var = s2 * (1.f / H_DIM) - mu * mu;
    float inv = rsqrtf(var + LN_EPS);

    const float4 gm = *(const float4*)(gamma + h);
    const float4 bt = *(const float4*)(beta  + h);
    float4 o;
    o.x = (v.x - mu) * inv * gm.x + bt.x;
    o.y = (v.y - mu) * inv * gm.y + bt.y;
    o.z = (v.z - mu) * inv * gm.z + bt.z;
    o.w = (v.w - mu) * inv * gm.w + bt.w;
    *(float4*)(x + (size_t)r * H_DIM + h) = o;
}

// ---------------------------------------------------------------------------
extern "C" void kernel_launch(void* const* d_in, const int* in_sizes, int n_in,
                              void* d_out, int out_size)
{
    const float* text    = (const float*)d_in[0];
    const float* sstruct = (const float*)d_in[1];
    const int*   mask    = (const int*)  d_in[2];
    const float* gate_w  = (const float*)d_in[3];
    const float* gate_b  = (const float*)d_in[4];
    const float* gamma   = (const float*)d_in[5];
    const float* beta    = (const float*)d_in[6];

    float* enriched = (float*)d_out;
    float* gates    = (float*)d_out + (size_t)T_DIM * H_DIM;

    {
        dim3 grd(H_DIM / 32, S_DIM / 32);            // 16 x 4 = 64 blocks
        gs_kernel<<<grd, 256>>>(sstruct, gate_w);
    }
    {
        dim3 grd(H_DIM / HC, T_DIM / TT);            // 16 x 32 = 512 blocks
        fuse3_kernel<<<grd, 256>>>(text, sstruct, mask, gate_w, gate_b,
                                   enriched, gates);
    }
    {
        ln_kernel<<<T_DIM / 2, 256>>>(enriched, gamma, beta);
    }
}

// round 7
// speedup vs baseline: 1.3859x; 1.3859x over previous
#include <cuda_runtime.h>
#include <math.h>

#define T_DIM 1024
#define S_DIM 128
#define H_DIM 512
#define LN_EPS 1e-5f

// Scratch (allocation-free rule: __device__ globals)
__device__ float d_gt[T_DIM * H_DIM];   // text   @ wt^T  (1024 x 512)
__device__ float d_gs[S_DIM * H_DIM];   // struct @ ws^T  (128  x 512)

// ---------------------------------------------------------------------------
// High-ILP combined GEMM: C[r,n] = sum_k A[r,k] * W[n*1024 + woff + k]
// Combined rows: [0,1024) -> gt (text, woff 0), [1024,1152) -> gs (struct, 512)
// BM=64, BN=64, BK=16, 128 threads, micro-tile 4x8 (32 acc/thread).
// Smem double-buffered, transposed tiles (As[k][m], Bs[k][n]).
// Grid: (512/64) x (1152/64) = 8 x 18 = 144 blocks.
// ---------------------------------------------------------------------------
#define BM 64
#define BN 64
#define BK 16
#define KTILES (H_DIM / BK)     // 32
#define LDA 68                  // BM + 4 pad (float4-aligned, reduces conflicts)
#define LDB 68

__global__ __launch_bounds__(128) void gemm_all_kernel(
    const float* __restrict__ text, const float* __restrict__ sstruct,
    const float* __restrict__ W)
{
    __shared__ float As[2][BK][LDA];
    __shared__ float Bs[2][BK][LDB];

    const int tid = threadIdx.x;
    const int tm  = tid & 15;            // 0..15 -> 4 M-rows each
    const int tn  = tid >> 4;            // 0..7  -> 8 N-cols each
    const int bcol  = blockIdx.x * BN;
    const int browg = blockIdx.y * BM;

    const float* __restrict__ A;
    float* __restrict__ C;
    int arow, woff;
    if (browg < T_DIM) { A = text;    arow = browg;         woff = 0;     C = d_gt; }
    else               { A = sstruct; arow = browg - T_DIM; woff = H_DIM; C = d_gs; }

    // Global-load mapping: 64 rows x 16 cols = 256 float4; 2 per thread.
    // lin = tid + i*128: row = lin>>2 (0..63), c4 = (lin&3)*4 (0,4,8,12)
    const int lr0 = tid >> 2;
    const int lr1 = (tid + 128) >> 2;
    const int lc  = (tid & 3) * 4;

    const float* Ap0 = A + (size_t)(arow + lr0) * H_DIM + lc;
    const float* Ap1 = A + (size_t)(arow + lr1) * H_DIM + lc;
    const float* Wp0 = W + (size_t)(bcol + lr0) * 1024 + woff + lc;
    const float* Wp1 = W + (size_t)(bcol + lr1) * 1024 + woff + lc;

    float acc[4][8];
    #pragma unroll
    for (int i = 0; i < 4; i++)
        #pragma unroll
        for (int j = 0; j < 8; j++) acc[i][j] = 0.f;

    // Prefetch tile 0
    float4 pa0 = *(const float4*)(Ap0);
    float4 pa1 = *(const float4*)(Ap1);
    float4 pb0 = *(const float4*)(Wp0);
    float4 pb1 = *(const float4*)(Wp1);

    // Store tile 0 into buffer 0 (transposed)
    #pragma unroll
    for (int j = 0; j < 4; j++) {
        As[0][lc + j][lr0] = ((const float*)&pa0)[j];
        As[0][lc + j][lr1] = ((const float*)&pa1)[j];
        Bs[0][lc + j][lr0] = ((const float*)&pb0)[j];
        Bs[0][lc + j][lr1] = ((const float*)&pb1)[j];
    }
    __syncthreads();

    #pragma unroll 1
    for (int kt = 0; kt < KTILES; kt++) {
        const int cur = kt & 1;
        const int nxt = cur ^ 1;

        if (kt + 1 < KTILES) {
            const int ko = (kt + 1) * BK;
            pa0 = *(const float4*)(Ap0 + ko);
            pa1 = *(const float4*)(Ap1 + ko);
            pb0 = *(const float4*)(Wp0 + ko);
            pb1 = *(const float4*)(Wp1 + ko);
        }

        #pragma unroll
        for (int k = 0; k < BK; k++) {
            float4 a4 = *(const float4*)&As[cur][k][tm * 4];
            float4 b0 = *(const float4*)&Bs[cur][k][tn * 8];
            float4 b1 = *(const float4*)&Bs[cur][k][tn * 8 + 4];
            const float a[4] = {a4.x, a4.y, a4.z, a4.w};
            const float b[8] = {b0.x, b0.y, b0.z, b0.w, b1.x, b1.y, b1.z, b1.w};
            #pragma unroll
            for (int i = 0; i < 4; i++)
                #pragma unroll
                for (int j = 0; j < 8; j++)
                    acc[i][j] = fmaf(a[i], b[j], acc[i][j]);
        }

        if (kt + 1 < KTILES) {
            #pragma unroll
            for (int j = 0; j < 4; j++) {
                As[nxt][lc + j][lr0] = ((const float*)&pa0)[j];
                As[nxt][lc + j][lr1] = ((const float*)&pa1)[j];
                Bs[nxt][lc + j][lr0] = ((const float*)&pb0)[j];
                Bs[nxt][lc + j][lr1] = ((const float*)&pb1)[j];
            }
            __syncthreads();
        }
    }

    #pragma unroll
    for (int i = 0; i < 4; i++) {
        float* Crow = C + (size_t)(arow + tm * 4 + i) * H_DIM + bcol + tn * 8;
        *(float4*)(Crow)     = make_float4(acc[i][0], acc[i][1], acc[i][2], acc[i][3]);
        *(float4*)(Crow + 4) = make_float4(acc[i][4], acc[i][5], acc[i][6], acc[i][7]);
    }
}

// ---------------------------------------------------------------------------
// fuse2 (round-4 version, measured ~93% of HBM): store-only hot loop.
// Grid: x = H/HC (16), y = T/TT (16) -> 256 blocks, 256 threads.
// ---------------------------------------------------------------------------
#define HC 32   // floats per h-chunk
#define TT 64   // t-rows per block

__global__ __launch_bounds__(256) void fuse2_kernel(
    const float* __restrict__ text,
    const float* __restrict__ sstruct,
    const int*   __restrict__ mask,
    const float* __restrict__ gate_b,
    float* __restrict__ xout,       // (T, H) = text + enrichment (pre-LN)
    float* __restrict__ gates)      // (T, S, H)
{
    __shared__ float gs_s[S_DIM][HC];
    __shared__ float st_s[S_DIM][HC];

    const int tid = threadIdx.x;
    const int hx  = tid & 7;
    const int ts  = tid >> 3;
    const int h0  = blockIdx.x * HC;
    const int t0  = blockIdx.y * TT;

    #pragma unroll
    for (int i = tid; i < S_DIM * (HC / 4); i += 256) {
        int s  = i >> 3;
        int c4 = (i & 7) * 4;
        *(float4*)&gs_s[s][c4] = *(const float4*)(d_gs    + (size_t)s * H_DIM + h0 + c4);
        *(float4*)&st_s[s][c4] = *(const float4*)(sstruct + (size_t)s * H_DIM + h0 + c4);
    }
    __syncthreads();

    const int h  = h0 + hx * 4;
    const int r0 = t0 + ts;
    const int r1 = t0 + ts + 32;

    const float4 bias = *(const float4*)(gate_b + h);

    float4 gtb0, gtb1;
    {
        float4 a = *(const float4*)(d_gt + (size_t)r0 * H_DIM + h);
        float4 b = *(const float4*)(d_gt + (size_t)r1 * H_DIM + h);
        gtb0 = make_float4(a.x + bias.x, a.y + bias.y, a.z + bias.z, a.w + bias.w);
        gtb1 = make_float4(b.x + bias.x, b.y + bias.y, b.z + bias.z, b.w + bias.w);
    }
    float4 acc0 = make_float4(0.f, 0.f, 0.f, 0.f);
    float4 acc1 = make_float4(0.f, 0.f, 0.f, 0.f);

    const int* __restrict__ m0p = mask + (size_t)r0 * S_DIM;
    const int* __restrict__ m1p = mask + (size_t)r1 * S_DIM;
    float* __restrict__ g0p = gates + (size_t)r0 * S_DIM * H_DIM + h;
    float* __restrict__ g1p = gates + (size_t)r1 * S_DIM * H_DIM + h;

    #pragma unroll 4
    for (int s = 0; s < S_DIM; s++) {
        const float4 gs4 = *(const float4*)&gs_s[s][hx * 4];
        const float4 sv4 = *(const float4*)&st_s[s][hx * 4];
        const bool m0 = (m0p[s] != 0);
        const bool m1 = (m1p[s] != 0);

        float4 g0, g1;
        g0.x = m0 ? fmaxf(gtb0.x + gs4.x, 0.f) : 0.f;
        g0.y = m0 ? fmaxf(gtb0.y + gs4.y, 0.f) : 0.f;
        g0.z = m0 ? fmaxf(gtb0.z + gs4.z, 0.f) : 0.f;
        g0.w = m0 ? fmaxf(gtb0.w + gs4.w, 0.f) : 0.f;
        g1.x = m1 ? fmaxf(gtb1.x + gs4.x, 0.f) : 0.f;
        g1.y = m1 ? fmaxf(gtb1.y + gs4.y, 0.f) : 0.f;
        g1.z = m1 ? fmaxf(gtb1.z + gs4.z, 0.f) : 0.f;
        g1.w = m1 ? fmaxf(gtb1.w + gs4.w, 0.f) : 0.f;

        __stcs((float4*)(g0p + (size_t)s * H_DIM), g0);
        __stcs((float4*)(g1p + (size_t)s * H_DIM), g1);

        acc0.x = fmaf(g0.x, sv4.x, acc0.x);
        acc0.y = fmaf(g0.y, sv4.y, acc0.y);
        acc0.z = fmaf(g0.z, sv4.z, acc0.z);
        acc0.w = fmaf(g0.w, sv4.w, acc0.w);
        acc1.x = fmaf(g1.x, sv4.x, acc1.x);
        acc1.y = fmaf(g1.y, sv4.y, acc1.y);
        acc1.z = fmaf(g1.z, sv4.z, acc1.z);
        acc1.w = fmaf(g1.w, sv4.w, acc1.w);
    }

    {
        float4 t4 = *(const float4*)(text + (size_t)r0 * H_DIM + h);
        *(float4*)(xout + (size_t)r0 * H_DIM + h) =
            make_float4(t4.x + acc0.x, t4.y + acc0.y, t4.z + acc0.z, t4.w + acc0.w);
    }
    {
        float4 t4 = *(const float4*)(text + (size_t)r1 * H_DIM + h);
        *(float4*)(xout + (size_t)r1 * H_DIM + h) =
            make_float4(t4.x + acc1.x, t4.y + acc1.y, t4.z + acc1.z, t4.w + acc1.w);
    }
}

// ---------------------------------------------------------------------------
// In-place LayerNorm. 256 threads, 2 rows per block.
// ---------------------------------------------------------------------------
__global__ __launch_bounds__(256) void ln_kernel(
    float* __restrict__ x,
    const float* __restrict__ gamma,
    const float* __restrict__ beta)
{
    const int tid = threadIdx.x;
    const int h4  = tid & 127;
    const int tg  = tid >> 7;
    const int h   = h4 * 4;
    const int r   = blockIdx.x * 2 + tg;

    __shared__ float red[2][2][4];

    float4 v = *(const float4*)(x + (size_t)r * H_DIM + h);
    float s1 = v.x + v.y + v.z + v.w;
    float s2 = v.x * v.x + v.y * v.y + v.z * v.z + v.w * v.w;

    const int lane = tid & 31;
    const int wg   = (tid >> 5) & 3;
    #pragma unroll
    for (int o = 16; o > 0; o >>= 1) {
        s1 += __shfl_xor_sync(0xFFFFFFFFu, s1, o);
        s2 += __shfl_xor_sync(0xFFFFFFFFu, s2, o);
    }
    if (lane == 0) { red[0][tg][wg] = s1; red[1][tg][wg] = s2; }
    __syncthreads();

    s1 = red[0][tg][0] + red[0][tg][1] + red[0][tg][2] + red[0][tg][3];
    s2 = red[1][tg][0] + red[1][tg][1] + red[1][tg][2] + red[1][tg][3];
    float mu  = s1 * (1.f / H_DIM);
    float var = s2 * (1.f / H_DIM) - mu * mu;
    float inv = rsqrtf(var + LN_EPS);

    const float4 gm = *(const float4*)(gamma + h);
    const float4 bt = *(const float4*)(beta  + h);
    float4 o;
    o.x = (v.x - mu) * inv * gm.x + bt.x;
    o.y = (v.y - mu) * inv * gm.y + bt.y;
    o.z = (v.z - mu) * inv * gm.z + bt.z;
    o.w = (v.w - mu) * inv * gm.w + bt.w;
    *(float4*)(x + (size_t)r * H_DIM + h) = o;
}

// ---------------------------------------------------------------------------
extern "C" void kernel_launch(void* const* d_in, const int* in_sizes, int n_in,
                              void* d_out, int out_size)
{
    const float* text    = (const float*)d_in[0];
    const float* sstruct = (const float*)d_in[1];
    const int*   mask    = (const int*)  d_in[2];
    const float* gate_w  = (const float*)d_in[3];
    const float* gate_b  = (const float*)d_in[4];
    const float* gamma   = (const float*)d_in[5];
    const float* beta    = (const float*)d_in[6];

    float* enriched = (float*)d_out;
    float* gates    = (float*)d_out + (size_t)T_DIM * H_DIM;

    {
        dim3 grd(H_DIM / BN, (T_DIM + S_DIM) / BM);   // 8 x 18 = 144 blocks
        gemm_all_kernel<<<grd, 128>>>(text, sstruct, gate_w);
    }
    {
        dim3 grd(H_DIM / HC, T_DIM / TT);             // 16 x 16 = 256 blocks
        fuse2_kernel<<<grd, 256>>>(text, sstruct, mask, gate_b,
                                   enriched, gates);
    }
    {
        ln_kernel<<<T_DIM / 2, 256>>>(enriched, gamma, beta);
    }
}

// round 8
// speedup vs baseline: 1.4556x; 1.0503x over previous
#include <cuda_runtime.h>
#include <math.h>

#define T_DIM 1024
#define S_DIM 128
#define H_DIM 512
#define LN_EPS 1e-5f

// Scratch (allocation-free rule: __device__ globals)
__device__ float d_gt[T_DIM * H_DIM];   // text   @ wt^T  (1024 x 512)
__device__ float d_gs[S_DIM * H_DIM];   // struct @ ws^T  (128  x 512)

// ---------------------------------------------------------------------------
// Combined GEMM: C[r,n] = sum_k A[r,k] * W[n*1024 + woff + k]
// Rows [0,1024) -> gt (text), [1024,1152) -> gs (struct).
// BM=64, BN=64, BK=16, 256 threads, micro-tile 4x4 (16 acc/thread).
// Double-buffered transposed smem; 2 warps/SMSP for FFMA latency hiding.
// Grid: 8 x 18 = 144 blocks.
// ---------------------------------------------------------------------------
#define BM 64
#define BN 64
#define BK 16
#define KTILES (H_DIM / BK)     // 32
#define LDA 68                  // BM + 4 pad

__global__ __launch_bounds__(256) void gemm_all_kernel(
    const float* __restrict__ text, const float* __restrict__ sstruct,
    const float* __restrict__ W)
{
    __shared__ float As[2][BK][LDA];
    __shared__ float Bs[2][BK][LDA];

    const int tid = threadIdx.x;
    const int tm  = tid & 15;            // 0..15 -> 4 M-rows each
    const int tn  = tid >> 4;            // 0..15 -> 4 N-cols each
    const int bcol  = blockIdx.x * BN;
    const int browg = blockIdx.y * BM;

    const float* __restrict__ A;
    float* __restrict__ C;
    int arow, woff;
    if (browg < T_DIM) { A = text;    arow = browg;         woff = 0;     C = d_gt; }
    else               { A = sstruct; arow = browg - T_DIM; woff = H_DIM; C = d_gs; }

    // Global-load mapping: 64 rows x 16 cols = 256 float4; 1 per thread.
    const int lr = tid >> 2;             // 0..63
    const int lc = (tid & 3) * 4;        // 0,4,8,12

    const float* Ap = A + (size_t)(arow + lr) * H_DIM + lc;
    const float* Wp = W + (size_t)(bcol + lr) * 1024 + woff + lc;

    float acc[4][4];
    #pragma unroll
    for (int i = 0; i < 4; i++)
        #pragma unroll
        for (int j = 0; j < 4; j++) acc[i][j] = 0.f;

    // Prefetch tile 0 and stage into buffer 0 (transposed: [k][row])
    float4 pa = *(const float4*)(Ap);
    float4 pb = *(const float4*)(Wp);
    #pragma unroll
    for (int j = 0; j < 4; j++) {
        As[0][lc + j][lr] = ((const float*)&pa)[j];
        Bs[0][lc + j][lr] = ((const float*)&pb)[j];
    }
    __syncthreads();

    #pragma unroll 1
    for (int kt = 0; kt < KTILES; kt++) {
        const int cur = kt & 1;
        const int nxt = cur ^ 1;

        if (kt + 1 < KTILES) {
            const int ko = (kt + 1) * BK;
            pa = *(const float4*)(Ap + ko);
            pb = *(const float4*)(Wp + ko);
        }

        #pragma unroll
        for (int k = 0; k < BK; k++) {
            float4 a4 = *(const float4*)&As[cur][k][tm * 4];
            float4 b4 = *(const float4*)&Bs[cur][k][tn * 4];
            const float a[4] = {a4.x, a4.y, a4.z, a4.w};
            const float b[4] = {b4.x, b4.y, b4.z, b4.w};
            #pragma unroll
            for (int i = 0; i < 4; i++)
                #pragma unroll
                for (int j = 0; j < 4; j++)
                    acc[i][j] = fmaf(a[i], b[j], acc[i][j]);
        }

        if (kt + 1 < KTILES) {
            #pragma unroll
            for (int j = 0; j < 4; j++) {
                As[nxt][lc + j][lr] = ((const float*)&pa)[j];
                Bs[nxt][lc + j][lr] = ((const float*)&pb)[j];
            }
            __syncthreads();
        }
    }

    #pragma unroll
    for (int i = 0; i < 4; i++) {
        float* Crow = C + (size_t)(arow + tm * 4 + i) * H_DIM + bcol + tn * 4;
        *(float4*)(Crow) = make_float4(acc[i][0], acc[i][1], acc[i][2], acc[i][3]);
    }
}

// ---------------------------------------------------------------------------
// fuse2 (measured ~93% of HBM): store-only hot loop.
// Grid: x = H/HC (16), y = T/TT (16) -> 256 blocks, 256 threads.
// ---------------------------------------------------------------------------
#define HC 32   // floats per h-chunk
#define TT 64   // t-rows per block

__global__ __launch_bounds__(256) void fuse2_kernel(
    const float* __restrict__ text,
    const float* __restrict__ sstruct,
    const int*   __restrict__ mask,
    const float* __restrict__ gate_b,
    float* __restrict__ xout,       // (T, H) = text + enrichment (pre-LN)
    float* __restrict__ gates)      // (T, S, H)
{
    __shared__ float gs_s[S_DIM][HC];
    __shared__ float st_s[S_DIM][HC];

    const int tid = threadIdx.x;
    const int hx  = tid & 7;
    const int ts  = tid >> 3;
    const int h0  = blockIdx.x * HC;
    const int t0  = blockIdx.y * TT;

    #pragma unroll
    for (int i = tid; i < S_DIM * (HC / 4); i += 256) {
        int s  = i >> 3;
        int c4 = (i & 7) * 4;
        *(float4*)&gs_s[s][c4] = *(const float4*)(d_gs    + (size_t)s * H_DIM + h0 + c4);
        *(float4*)&st_s[s][c4] = *(const float4*)(sstruct + (size_t)s * H_DIM + h0 + c4);
    }
    __syncthreads();

    const int h  = h0 + hx * 4;
    const int r0 = t0 + ts;
    const int r1 = t0 + ts + 32;

    const float4 bias = *(const float4*)(gate_b + h);

    float4 gtb0, gtb1;
    {
        float4 a = *(const float4*)(d_gt + (size_t)r0 * H_DIM + h);
        float4 b = *(const float4*)(d_gt + (size_t)r1 * H_DIM + h);
        gtb0 = make_float4(a.x + bias.x, a.y + bias.y, a.z + bias.z, a.w + bias.w);
        gtb1 = make_float4(b.x + bias.x, b.y + bias.y, b.z + bias.z, b.w + bias.w);
    }
    float4 acc0 = make_float4(0.f, 0.f, 0.f, 0.f);
    float4 acc1 = make_float4(0.f, 0.f, 0.f, 0.f);

    const int* __restrict__ m0p = mask + (size_t)r0 * S_DIM;
    const int* __restrict__ m1p = mask + (size_t)r1 * S_DIM;
    float* __restrict__ g0p = gates + (size_t)r0 * S_DIM * H_DIM + h;
    float* __restrict__ g1p = gates + (size_t)r1 * S_DIM * H_DIM + h;

    #pragma unroll 4
    for (int s = 0; s < S_DIM; s++) {
        const float4 gs4 = *(const float4*)&gs_s[s][hx * 4];
        const float4 sv4 = *(const float4*)&st_s[s][hx * 4];
        const bool m0 = (m0p[s] != 0);
        const bool m1 = (m1p[s] != 0);

        float4 g0, g1;
        g0.x = m0 ? fmaxf(gtb0.x + gs4.x, 0.f) : 0.f;
        g0.y = m0 ? fmaxf(gtb0.y + gs4.y, 0.f) : 0.f;
        g0.z = m0 ? fmaxf(gtb0.z + gs4.z, 0.f) : 0.f;
        g0.w = m0 ? fmaxf(gtb0.w + gs4.w, 0.f) : 0.f;
        g1.x = m1 ? fmaxf(gtb1.x + gs4.x, 0.f) : 0.f;
        g1.y = m1 ? fmaxf(gtb1.y + gs4.y, 0.f) : 0.f;
        g1.z = m1 ? fmaxf(gtb1.z + gs4.z, 0.f) : 0.f;
        g1.w = m1 ? fmaxf(gtb1.w + gs4.w, 0.f) : 0.f;

        __stcs((float4*)(g0p + (size_t)s * H_DIM), g0);
        __stcs((float4*)(g1p + (size_t)s * H_DIM), g1);

        acc0.x = fmaf(g0.x, sv4.x, acc0.x);
        acc0.y = fmaf(g0.y, sv4.y, acc0.y);
        acc0.z = fmaf(g0.z, sv4.z, acc0.z);
        acc0.w = fmaf(g0.w, sv4.w, acc0.w);
        acc1.x = fmaf(g1.x, sv4.x, acc1.x);
        acc1.y = fmaf(g1.y, sv4.y, acc1.y);
        acc1.z = fmaf(g1.z, sv4.z, acc1.z);
        acc1.w = fmaf(g1.w, sv4.w, acc1.w);
    }

    {
        float4 t4 = *(const float4*)(text + (size_t)r0 * H_DIM + h);
        *(float4*)(xout + (size_t)r0 * H_DIM + h) =
            make_float4(t4.x + acc0.x, t4.y + acc0.y, t4.z + acc0.z, t4.w + acc0.w);
    }
    {
        float4 t4 = *(const float4*)(text + (size_t)r1 * H_DIM + h);
        *(float4*)(xout + (size_t)r1 * H_DIM + h) =
            make_float4(t4.x + acc1.x, t4.y + acc1.y, t4.z + acc1.z, t4.w + acc1.w);
    }
}

// ---------------------------------------------------------------------------
// In-place LayerNorm. 256 threads, 2 rows per block.
// ---------------------------------------------------------------------------
__global__ __launch_bounds__(256) void ln_kernel(
    float* __restrict__ x,
    const float* __restrict__ gamma,
    const float* __restrict__ beta)
{
    const int tid = threadIdx.x;
    const int h4  = tid & 127;
    const int tg  = tid >> 7;
    const int h   = h4 * 4;
    const int r   = blockIdx.x * 2 + tg;

    __shared__ float red[2][2][4];

    float4 v = *(const float4*)(x + (size_t)r * H_DIM + h);
    float s1 = v.x + v.y + v.z + v.w;
    float s2 = v.x * v.x + v.y * v.y + v.z * v.z + v.w * v.w;

    const int lane = tid & 31;
    const int wg   = (tid >> 5) & 3;
    #pragma unroll
    for (int o = 16; o > 0; o >>= 1) {
        s1 += __shfl_xor_sync(0xFFFFFFFFu, s1, o);
        s2 += __shfl_xor_sync(0xFFFFFFFFu, s2, o);
    }
    if (lane == 0) { red[0][tg][wg] = s1; red[1][tg][wg] = s2; }
    __syncthreads();

    s1 = red[0][tg][0] + red[0][tg][1] + red[0][tg][2] + red[0][tg][3];
    s2 = red[1][tg][0] + red[1][tg][1] + red[1][tg][2] + red[1][tg][3];
    float mu  = s1 * (1.f / H_DIM);
    float var = s2 * (1.f / H_DIM) - mu * mu;
    float inv = rsqrtf(var + LN_EPS);

    const float4 gm = *(const float4*)(gamma + h);
    const float4 bt = *(const float4*)(beta  + h);
    float4 o;
    o.x = (v.x - mu) * inv * gm.x + bt.x;
    o.y = (v.y - mu) * inv * gm.y + bt.y;
    o.z = (v.z - mu) * inv * gm.z + bt.z;
    o.w = (v.w - mu) * inv * gm.w + bt.w;
    *(float4*)(x + (size_t)r * H_DIM + h) = o;
}

// ---------------------------------------------------------------------------
extern "C" void kernel_launch(void* const* d_in, const int* in_sizes, int n_in,
                              void* d_out, int out_size)
{
    const float* text    = (const float*)d_in[0];
    const float* sstruct = (const float*)d_in[1];
    const int*   mask    = (const int*)  d_in[2];
    const float* gate_w  = (const float*)d_in[3];
    const float* gate_b  = (const float*)d_in[4];
    const float* gamma   = (const float*)d_in[5];
    const float* beta    = (const float*)d_in[6];

    float* enriched = (float*)d_out;
    float* gates    = (float*)d_out + (size_t)T_DIM * H_DIM;

    {
        dim3 grd(H_DIM / BN, (T_DIM + S_DIM) / BM);   // 8 x 18 = 144 blocks
        gemm_all_kernel<<<grd, 256>>>(text, sstruct, gate_w);
    }
    {
        dim3 grd(H_DIM / HC, T_DIM / TT);             // 16 x 16 = 256 blocks
        fuse2_kernel<<<grd, 256>>>(text, sstruct, mask, gate_b,
                                   enriched, gates);
    }
    {
        ln_kernel<<<T_DIM / 2, 256>>>(enriched, gamma, beta);
    }
}